// round 1
// baseline (speedup 1.0000x reference)
#include <cuda_runtime.h>

// IoU3DLoss: per-pair rotated 3D IoU -> mean((1-iou)*weight)
// Inputs (metadata order): pred [N,7] f32, target [N,7] f32, weight [N] f32
// Output: scalar f32.

constexpr int BLOCK = 256;
constexpr int MAX_PARTIALS = 8192;

__device__ float g_partial[MAX_PARTIALS];

__global__ void __launch_bounds__(BLOCK)
iou3d_loss_kernel(const float* __restrict__ pred,
                  const float* __restrict__ target,
                  const float* __restrict__ weight,
                  int N)
{
    int i = blockIdx.x * BLOCK + threadIdx.x;
    float loss = 0.0f;

    if (i < N) {
        // Load the two boxes: [x, y, z, w, h, dz, yaw]
        const float* b1 = pred + (size_t)i * 7;
        const float* b2 = target + (size_t)i * 7;
        float x1 = b1[0], y1 = b1[1], z1 = b1[2], w1 = b1[3], h1 = b1[4], d1 = b1[5], a1 = b1[6];
        float x2 = b2[0], y2 = b2[1], z2 = b2[2], w2 = b2[3], h2 = b2[4], d2 = b2[5], a2 = b2[6];

        // Corner offsets (CCW): tx = {.5,-.5,-.5,.5}, ty = {.5,.5,-.5,-.5}
        const float tx[4] = {0.5f, -0.5f, -0.5f, 0.5f};
        const float ty[4] = {0.5f, 0.5f, -0.5f, -0.5f};

        // Subject polygon = box1 corners
        float px[10], py[10];
        {
            float s, c;
            sincosf(a1, &s, &c);
            #pragma unroll
            for (int k = 0; k < 4; k++) {
                float xx = tx[k] * w1;
                float yy = ty[k] * h1;
                px[k] = c * xx - s * yy + x1;
                py[k] = s * xx + c * yy + y1;
            }
        }
        // Clip polygon = box2 corners
        float cx2[4], cy2[4];
        {
            float s, c;
            sincosf(a2, &s, &c);
            #pragma unroll
            for (int k = 0; k < 4; k++) {
                float xx = tx[k] * w2;
                float yy = ty[k] * h2;
                cx2[k] = c * xx - s * yy + x2;
                cy2[k] = s * xx + c * yy + y2;
            }
        }

        // Sutherland-Hodgman: clip subject (CCW) against each edge of box2 (CCW).
        // Interior is on the LEFT of each directed edge: cross(e, p-a) >= 0.
        int n = 4;
        float qx[10], qy[10];
        for (int e = 0; e < 4; e++) {
            if (n == 0) break;
            float ax = cx2[e],         ay = cy2[e];
            float bx = cx2[(e + 1) & 3], by = cy2[(e + 1) & 3];
            float ex = bx - ax, ey = by - ay;

            int m = 0;
            float xprev = px[n - 1], yprev = py[n - 1];
            float dprev = ex * (yprev - ay) - ey * (xprev - ax);
            for (int k = 0; k < n; k++) {
                float xc = px[k], yc = py[k];
                float dc = ex * (yc - ay) - ey * (xc - ax);
                bool in_c = (dc >= 0.0f);
                bool in_p = (dprev >= 0.0f);
                if (in_c != in_p) {
                    float t = dprev / (dprev - dc);
                    qx[m] = xprev + t * (xc - xprev);
                    qy[m] = yprev + t * (yc - yprev);
                    m++;
                }
                if (in_c) {
                    qx[m] = xc;
                    qy[m] = yc;
                    m++;
                }
                dprev = dc; xprev = xc; yprev = yc;
            }
            n = m;
            for (int k = 0; k < n; k++) { px[k] = qx[k]; py[k] = qy[k]; }
        }

        // Shoelace area of the intersection polygon
        float area2 = 0.0f;
        if (n >= 3) {
            float xp = px[n - 1], yp = py[n - 1];
            for (int k = 0; k < n; k++) {
                area2 += xp * py[k] - px[k] * yp;
                xp = px[k]; yp = py[k];
            }
        }
        float inter2d = 0.5f * fabsf(area2);

        // z overlap
        float zmax = fminf(z1 + 0.5f * d1, z2 + 0.5f * d2);
        float zmin = fmaxf(z1 - 0.5f * d1, z2 - 0.5f * d2);
        float inter3d = inter2d * fmaxf(zmax - zmin, 0.0f);

        float v1 = w1 * h1 * d1;
        float v2 = w2 * h2 * d2;
        float iou = inter3d / (v1 + v2 - inter3d + 1e-8f);

        loss = (1.0f - iou) * weight[i];
    }

    // Block reduction: warp shuffle -> shared -> one partial per block
    #pragma unroll
    for (int off = 16; off > 0; off >>= 1)
        loss += __shfl_xor_sync(0xffffffffu, loss, off);

    __shared__ float smem[BLOCK / 32];
    if ((threadIdx.x & 31) == 0) smem[threadIdx.x >> 5] = loss;
    __syncthreads();

    if (threadIdx.x < BLOCK / 32) {
        float v = smem[threadIdx.x];
        #pragma unroll
        for (int off = (BLOCK / 64); off > 0; off >>= 1)
            v += __shfl_xor_sync(0xffu, v, off);
        if (threadIdx.x == 0) g_partial[blockIdx.x] = v;
    }
}

__global__ void __launch_bounds__(256)
iou3d_finalize_kernel(float* __restrict__ out, int nparts, float inv_n)
{
    float s = 0.0f;
    for (int k = threadIdx.x; k < nparts; k += 256)
        s += g_partial[k];

    #pragma unroll
    for (int off = 16; off > 0; off >>= 1)
        s += __shfl_xor_sync(0xffffffffu, s, off);

    __shared__ float smem[8];
    if ((threadIdx.x & 31) == 0) smem[threadIdx.x >> 5] = s;
    __syncthreads();

    if (threadIdx.x == 0) {
        float v = 0.0f;
        #pragma unroll
        for (int w = 0; w < 8; w++) v += smem[w];
        out[0] = v * inv_n;
    }
}

extern "C" void kernel_launch(void* const* d_in, const int* in_sizes, int n_in,
                              void* d_out, int out_size)
{
    const float* pred   = (const float*)d_in[0];
    const float* target = (const float*)d_in[1];
    const float* weight = (const float*)d_in[2];
    int N = in_sizes[2];  // weight element count == number of boxes

    int grid = (N + BLOCK - 1) / BLOCK;
    if (grid > MAX_PARTIALS) grid = MAX_PARTIALS;  // N=1M -> 4096 blocks, well within cap

    iou3d_loss_kernel<<<grid, BLOCK>>>(pred, target, weight, N);
    iou3d_finalize_kernel<<<1, 256>>>((float*)d_out, grid, 1.0f / (float)N);
}

// round 2
// speedup vs baseline: 4.3060x; 4.3060x over previous
#include <cuda_runtime.h>

// IoU3DLoss: per-pair rotated 3D IoU -> mean((1-iou)*weight)
// Branch-free Green's-theorem formulation:
//   2*InterArea = sum over { edges of A clipped inside B } U { edges of B clipped inside A }
//                 of cross(seg_start, seg_end)        (all in B's local frame, CCW)
// Each clip is a Liang-Barsky slab clip vs an axis-aligned box -> straight-line code,
// no vertex lists, no local memory, no divergence.

constexpr int BLOCK = 256;
constexpr int MAX_PARTIALS = 8192;

__device__ float g_partial[MAX_PARTIALS];

// t-interval of p0 + t*d with |coord| <= W.  Branchless: relies on IEEE inf.
__device__ __forceinline__ void slab_clip(float u0, float du, float W,
                                          float& lo, float& hi)
{
    float inv = __fdividef(1.0f, du);     // du==0 -> +/-inf; interval logic stays correct
    float ta = (-W - u0) * inv;
    float tb = ( W - u0) * inv;
    lo = fminf(ta, tb);
    hi = fmaxf(ta, tb);
}

// Clip segment (p0, p0+d) to axis box [+-W, +-H] given local coords (u0,v0,du,dv),
// evaluate endpoints in the *caller's* frame (p0x/p0y/dx/dy), return cross(start,end).
__device__ __forceinline__ float clipped_cross(float u0, float v0, float du, float dv,
                                               float W, float H,
                                               float p0x, float p0y, float dx, float dy)
{
    float lo1, hi1, lo2, hi2;
    slab_clip(u0, du, W, lo1, hi1);
    slab_clip(v0, dv, H, lo2, hi2);
    float tmin = fmaxf(fmaxf(lo1, lo2), 0.0f);
    float tmax = fminf(fminf(hi1, hi2), 1.0f);
    bool valid = (tmax > tmin);
    float ax = fmaf(tmin, dx, p0x), ay = fmaf(tmin, dy, p0y);
    float bx = fmaf(tmax, dx, p0x), by = fmaf(tmax, dy, p0y);
    float cr = ax * by - ay * bx;
    return valid ? cr : 0.0f;
}

__global__ void __launch_bounds__(BLOCK)
iou3d_loss_kernel(const float* __restrict__ pred,
                  const float* __restrict__ target,
                  const float* __restrict__ weight,
                  int N)
{
    int i = blockIdx.x * BLOCK + threadIdx.x;
    float loss = 0.0f;

    if (i < N) {
        const float* b1 = pred   + (size_t)i * 7;
        const float* b2 = target + (size_t)i * 7;
        float x1 = b1[0], y1 = b1[1], z1 = b1[2], w1 = b1[3], h1 = b1[4], d1 = b1[5], a1 = b1[6];
        float x2 = b2[0], y2 = b2[1], z2 = b2[2], w2 = b2[3], h2 = b2[4], d2 = b2[5], a2 = b2[6];

        // Work in B(target)'s local frame: B is the axis box [+-W2, +-H2],
        // A is a rect centered (cx,cy) at relative angle ar = a1-a2.
        float s2, c2; __sincosf(a2, &s2, &c2);        // fast-math sincos; see note below
        float sr, cr; __sincosf(a1 - a2, &sr, &cr);
        // Recompute with accurate sincos to keep rel_err tiny (cheap vs total work):
        sincosf(a2, &s2, &c2);
        sincosf(a1 - a2, &sr, &cr);

        float dx0 = x1 - x2, dy0 = y1 - y2;
        float cx =  c2 * dx0 + s2 * dy0;
        float cy = -s2 * dx0 + c2 * dy0;

        float W1 = 0.5f * w1, H1 = 0.5f * h1;
        float W2 = 0.5f * w2, H2 = 0.5f * h2;

        // A's half-edge vectors in B-frame
        float ex = cr * W1, ey = sr * W1;     // along A's local x
        float fx = -sr * H1, fy = cr * H1;    // along A's local y

        // A corners, CCW (matches reference order): c+e+f, c-e+f, c-e-f, c+e-f
        float Ax0 = cx + ex + fx, Ay0 = cy + ey + fy;
        float Ax1 = cx - ex + fx, Ay1 = cy - ey + fy;
        float Ax2 = cx - ex - fx, Ay2 = cy - ey - fy;
        float Ax3 = cx + ex - fx, Ay3 = cy + ey - fy;

        float area2 = 0.0f;

        // ---- Edges of A clipped against box B (B-local coords == B-frame coords)
        {
            // edge macro-expansion via 4 explicit calls (keeps everything in registers)
            float px, py, qx, qy, dxe, dye;
            px = Ax0; py = Ay0; qx = Ax1; qy = Ay1; dxe = qx - px; dye = qy - py;
            area2 += clipped_cross(px, py, dxe, dye, W2, H2, px, py, dxe, dye);
            px = Ax1; py = Ay1; qx = Ax2; qy = Ay2; dxe = qx - px; dye = qy - py;
            area2 += clipped_cross(px, py, dxe, dye, W2, H2, px, py, dxe, dye);
            px = Ax2; py = Ay2; qx = Ax3; qy = Ay3; dxe = qx - px; dye = qy - py;
            area2 += clipped_cross(px, py, dxe, dye, W2, H2, px, py, dxe, dye);
            px = Ax3; py = Ay3; qx = Ax0; qy = Ay0; dxe = qx - px; dye = qy - py;
            area2 += clipped_cross(px, py, dxe, dye, W2, H2, px, py, dxe, dye);
        }

        // ---- Edges of B clipped against box A (transform into A-local coords)
        {
            // B corners CCW: (W2,H2), (-W2,H2), (-W2,-H2), (W2,-H2)
            const float Bx[4] = { W2, -W2, -W2,  W2 };
            const float By[4] = { H2,  H2, -H2, -H2 };
            #pragma unroll
            for (int k = 0; k < 4; k++) {
                float p0x = Bx[k], p0y = By[k];
                float p1x = Bx[(k + 1) & 3], p1y = By[(k + 1) & 3];
                float dxe = p1x - p0x, dye = p1y - p0y;
                // A-local coords of start point and direction (rotation by -ar, translate)
                float rx = p0x - cx, ry = p0y - cy;
                float u0 =  cr * rx + sr * ry;
                float v0 = -sr * rx + cr * ry;
                float du =  cr * dxe + sr * dye;
                float dv = -sr * dxe + cr * dye;
                area2 += clipped_cross(u0, v0, du, dv, W1, H1, p0x, p0y, dxe, dye);
            }
        }

        float inter2d = 0.5f * fabsf(area2);

        float zmax = fminf(z1 + 0.5f * d1, z2 + 0.5f * d2);
        float zmin = fmaxf(z1 - 0.5f * d1, z2 - 0.5f * d2);
        float inter3d = inter2d * fmaxf(zmax - zmin, 0.0f);

        float v1 = w1 * h1 * d1;
        float v2 = w2 * h2 * d2;
        float iou = inter3d / (v1 + v2 - inter3d + 1e-8f);

        loss = (1.0f - iou) * weight[i];
    }

    // Block reduction: warp shuffle -> shared -> one partial per block
    #pragma unroll
    for (int off = 16; off > 0; off >>= 1)
        loss += __shfl_xor_sync(0xffffffffu, loss, off);

    __shared__ float smem[BLOCK / 32];
    if ((threadIdx.x & 31) == 0) smem[threadIdx.x >> 5] = loss;
    __syncthreads();

    if (threadIdx.x < BLOCK / 32) {
        float v = smem[threadIdx.x];
        #pragma unroll
        for (int off = (BLOCK / 64); off > 0; off >>= 1)
            v += __shfl_xor_sync(0xffu, v, off);
        if (threadIdx.x == 0) g_partial[blockIdx.x] = v;
    }
}

__global__ void __launch_bounds__(256)
iou3d_finalize_kernel(float* __restrict__ out, int nparts, float inv_n)
{
    float s = 0.0f;
    for (int k = threadIdx.x; k < nparts; k += 256)
        s += g_partial[k];

    #pragma unroll
    for (int off = 16; off > 0; off >>= 1)
        s += __shfl_xor_sync(0xffffffffu, s, off);

    __shared__ float smem[8];
    if ((threadIdx.x & 31) == 0) smem[threadIdx.x >> 5] = s;
    __syncthreads();

    if (threadIdx.x == 0) {
        float v = 0.0f;
        #pragma unroll
        for (int w = 0; w < 8; w++) v += smem[w];
        out[0] = v * inv_n;
    }
}

extern "C" void kernel_launch(void* const* d_in, const int* in_sizes, int n_in,
                              void* d_out, int out_size)
{
    const float* pred   = (const float*)d_in[0];
    const float* target = (const float*)d_in[1];
    const float* weight = (const float*)d_in[2];
    int N = in_sizes[2];

    int grid = (N + BLOCK - 1) / BLOCK;
    if (grid > MAX_PARTIALS) grid = MAX_PARTIALS;   // N=1M -> 4096 blocks

    iou3d_loss_kernel<<<grid, BLOCK>>>(pred, target, weight, N);
    iou3d_finalize_kernel<<<1, 256>>>((float*)d_out, grid, 1.0f / (float)N);
}